// round 16
// baseline (speedup 1.0000x reference)
#include <cuda_runtime.h>
#include <cuda_fp16.h>
#include <mma.h>
#include <cstdint>

using namespace nvcuda;

#define N_NODES 100000
#define N_EDGES 1000000
#define H 128

// Scratch: per-node transformed features in fp16 (u = W1_src*z_src + b1, v = W1_dst*z_dst)
__device__ __half g_u[(size_t)N_NODES * H];
__device__ __half g_v[(size_t)N_NODES * H];

#define LDA 136
// Pre-converted W1 halves, already in the padded smem-image layout [n*LDA + k]
__device__ __half g_w1h[2][128 * LDA];

// ---- dynamic smem layout (MT=64 tiles) ----
// A fp16 [64][136]  at 0        (17408 B)   (epilogue wbufs reuse this region)
// B fp16 [128][136] at 17408    (34816 B)
// b1 f32 [128]      at 52224    (512 B)
#define S_A 0
#define S_B 17408
#define S_B1 52224
#define S_TOTAL 52736

// One-shot W1 fp32 -> fp16 into padded image, 4 elems/thread (float4 in, 2x half2 out).
__global__ __launch_bounds__(256)
void convert_w1_kernel(const float* __restrict__ W1)
{
    int flat = (blockIdx.x * 256 + threadIdx.x) * 4;   // 0..32764, step 4
    int h = flat >> 14;                                // 0: src half, 1: dst half
    int rem = flat & 16383;
    int n = rem >> 7;
    int k = rem & 127;                                 // multiple of 4
    float4 f = *(const float4*)&W1[n * (2 * H) + h * H + k];
    __half2 h0 = __float22half2_rn(make_float2(f.x, f.y));
    __half2 h1 = __float22half2_rn(make_float2(f.z, f.w));
    uint2 q;
    q.x = *(uint32_t*)&h0;
    q.y = *(uint32_t*)&h1;
    *(uint2*)&g_w1h[h][n * LDA + k] = q;
}

// Tensor-core (HMMA/wmma) node GEMM, MT=64: out[m,n] = sum_k A[m,k] * W[n, koff+k]
// fp16 inputs, fp32 accumulate, fp16 output. B staged via cp.async from the
// pre-converted fp16 image; epilogue reuses the A smem region.
// blockIdx.y==0: A=z_src, out=g_u (+b1); ==1: A=z_dst, out=g_v
__global__ __launch_bounds__(256)
void node_gemm_wmma(const float* __restrict__ zsrc,
                    const float* __restrict__ zdst,
                    const float* __restrict__ b1)
{
    extern __shared__ __align__(16) char smem[];
    __half* As  = (__half*)(smem + S_A);
    __half* Bs  = (__half*)(smem + S_B);
    float*  b1s = (float*)(smem + S_B1);

    const int tid = threadIdx.x;
    const int wid = tid >> 5;
    const int lane = tid & 31;
    const int mbase = blockIdx.x * 64;
    const bool is_src = (blockIdx.y == 0);
    const float* __restrict__ A = is_src ? zsrc : zdst;
    const __half* __restrict__ Bg = g_w1h[is_src ? 0 : 1];
    __half* __restrict__ out = is_src ? g_u : g_v;

    if (tid < 128) b1s[tid] = is_src ? b1[tid] : 0.f;

    // ---- stage B tile [128 x 128] via cp.async (16B chunks, overlaps A work) ----
    #pragma unroll
    for (int it = 0; it < 8; ++it) {
        int c = tid + it * 256;              // 2048 chunks of 8 halves
        int row = c >> 4;
        int chunk = (c & 15) * 8;
        uint32_t dst = (uint32_t)__cvta_generic_to_shared(&Bs[row * LDA + chunk]);
        const __half* src = &Bg[row * LDA + chunk];
        asm volatile("cp.async.ca.shared.global [%0], [%1], 16;" :: "r"(dst), "l"(src));
    }
    asm volatile("cp.async.commit_group;" ::: "memory");

    // ---- stage A tile [64 x 128] fp32 -> fp16, padded row-major ----
    #pragma unroll
    for (int it = 0; it < 4; ++it) {
        int c = tid + it * 256;          // 1024 chunks of 8 cols
        int row = c >> 4;
        int col = (c & 15) * 8;
        float4 f0 = make_float4(0.f, 0.f, 0.f, 0.f), f1 = f0;
        int mg = mbase + row;
        if (mg < N_NODES) {
            const float* src = A + (size_t)mg * H + col;
            f0 = *(const float4*)src;
            f1 = *(const float4*)(src + 4);
        }
        __half2 h0 = __float22half2_rn(make_float2(f0.x, f0.y));
        __half2 h1 = __float22half2_rn(make_float2(f0.z, f0.w));
        __half2 h2 = __float22half2_rn(make_float2(f1.x, f1.y));
        __half2 h3 = __float22half2_rn(make_float2(f1.z, f1.w));
        uint4 q;
        q.x = *(uint32_t*)&h0; q.y = *(uint32_t*)&h1;
        q.z = *(uint32_t*)&h2; q.w = *(uint32_t*)&h3;
        *(uint4*)&As[row * LDA + col] = q;
    }

    asm volatile("cp.async.wait_group 0;" ::: "memory");
    __syncthreads();

    // ---- wmma compute: warp (wm, wn) owns rows [wm*32, +32), cols [wn*32, +32) ----
    const int wm = wid & 1;
    const int wn = wid >> 1;

    wmma::fragment<wmma::accumulator, 16, 16, 16, float> acc[2][2];
    #pragma unroll
    for (int i = 0; i < 2; ++i)
        #pragma unroll
        for (int j = 0; j < 2; ++j)
            wmma::fill_fragment(acc[i][j], 0.f);

    #pragma unroll
    for (int ks = 0; ks < 128; ks += 16) {
        wmma::fragment<wmma::matrix_a, 16, 16, 16, __half, wmma::row_major> af[2];
        wmma::fragment<wmma::matrix_b, 16, 16, 16, __half, wmma::col_major> bf[2];
        #pragma unroll
        for (int i = 0; i < 2; ++i)
            wmma::load_matrix_sync(af[i], &As[(wm * 32 + 16 * i) * LDA + ks], LDA);
        #pragma unroll
        for (int j = 0; j < 2; ++j)
            wmma::load_matrix_sync(bf[j], &Bs[(wn * 32 + 16 * j) * LDA + ks], LDA);
        #pragma unroll
        for (int i = 0; i < 2; ++i)
            #pragma unroll
            for (int j = 0; j < 2; ++j)
                wmma::mma_sync(acc[i][j], af[i], bf[j], acc[i][j]);
    }

    __syncthreads();   // everyone done reading As/Bs; epilogue reuses A region

    // ---- epilogue from fragments via per-warp 16x16 staging tile (in A region) ----
    float* wbuf = (float*)(smem) + wid * 256;
    const int r  = lane >> 1;          // 0..15 row within fragment
    const int ch = lane & 1;           // 0/1 -> 8-col half
    #pragma unroll
    for (int i = 0; i < 2; ++i) {
        #pragma unroll
        for (int j = 0; j < 2; ++j) {
            wmma::store_matrix_sync(wbuf, acc[i][j], 16, wmma::mem_row_major);
            __syncwarp();
            const int m = mbase + wm * 32 + 16 * i + r;
            const int c0 = wn * 32 + 16 * j + ch * 8;
            if (m < N_NODES) {
                const float* cp = &wbuf[r * 16 + ch * 8];
                float4 f0 = *(const float4*)cp;
                float4 f1 = *(const float4*)(cp + 4);
                float4 g0 = *(const float4*)&b1s[c0];
                float4 g1 = *(const float4*)&b1s[c0 + 4];
                __half2 h0 = __float22half2_rn(make_float2(f0.x + g0.x, f0.y + g0.y));
                __half2 h1 = __float22half2_rn(make_float2(f0.z + g0.z, f0.w + g0.w));
                __half2 h2 = __float22half2_rn(make_float2(f1.x + g1.x, f1.y + g1.y));
                __half2 h3 = __float22half2_rn(make_float2(f1.z + g1.z, f1.w + g1.w));
                uint4 q;
                q.x = *(uint32_t*)&h0; q.y = *(uint32_t*)&h1;
                q.z = *(uint32_t*)&h2; q.w = *(uint32_t*)&h3;
                *(uint4*)&out[(size_t)m * H + c0] = q;
            }
            __syncwarp();
        }
    }
}

__device__ __forceinline__ __half2 h2_of(uint32_t u) { return *(__half2*)&u; }

// 8 edges per warp, 16 lanes per edge, LDG.128 row loads.
// out[e] = W2 . relu(u[row[e]] + v[col[e]]) + b2  (u,v fp16)
__global__ __launch_bounds__(256)
void edge_kernel(const int* __restrict__ eidx,
                 const float* __restrict__ W2,
                 const float* __restrict__ b2,
                 float* __restrict__ out)
{
    const int lane = threadIdx.x & 31;
    const int w = (int)((blockIdx.x * blockDim.x + threadIdx.x) >> 5);
    const int e0 = w * 8;
    if (e0 >= N_EDGES) return;

    const int hf  = lane >> 4;        // 0: edges e0..e0+3, 1: e0+4..e0+7
    const int sub = lane & 15;        // 16B chunk within the 256B row

    // per-lane weights: 8 consecutive W2 floats at sub*8 -> 4 half2
    const float4 wa = *(const float4*)&W2[sub * 8];
    const float4 wb = *(const float4*)&W2[sub * 8 + 4];
    const __half2 w0 = __floats2half2_rn(wa.x, wa.y);
    const __half2 w1 = __floats2half2_rn(wa.z, wa.w);
    const __half2 w2h = __floats2half2_rn(wb.x, wb.y);
    const __half2 w3 = __floats2half2_rn(wb.z, wb.w);
    const __half2 zero2 = __float2half2_rn(0.f);
    const float bb = __ldg(b2);

    // this half-warp's 4 edges
    const int4 rr = *(const int4*)&eidx[e0 + hf * 4];
    const int4 cc = *(const int4*)&eidx[N_EDGES + e0 + hf * 4];
    const int ridx[4] = {rr.x, rr.y, rr.z, rr.w};
    const int cidx[4] = {cc.x, cc.y, cc.z, cc.w};

    const uint4* __restrict__ up = (const uint4*)g_u;   // row = 16 uint4
    const uint4* __restrict__ vp = (const uint4*)g_v;

    float res[4];
    #pragma unroll
    for (int t = 0; t < 4; ++t) {
        const uint4 ua = up[(size_t)ridx[t] * 16 + sub];
        const uint4 va = vp[(size_t)cidx[t] * 16 + sub];

        __half2 t0 = __hmax2(__hadd2(h2_of(ua.x), h2_of(va.x)), zero2);
        __half2 t1 = __hmax2(__hadd2(h2_of(ua.y), h2_of(va.y)), zero2);
        __half2 t2 = __hmax2(__hadd2(h2_of(ua.z), h2_of(va.z)), zero2);
        __half2 t3 = __hmax2(__hadd2(h2_of(ua.w), h2_of(va.w)), zero2);

        // 2-deep half2 chains, combine in fp32
        __half2 p01 = __hfma2(t1, w1, __hmul2(t0, w0));
        __half2 p23 = __hfma2(t3, w3, __hmul2(t2, w2h));
        float2 f01 = __half22float2(p01);
        float2 f23 = __half22float2(p23);
        float s = (f01.x + f01.y) + (f23.x + f23.y);

        // 16-lane tree reduce (xor within half-warp)
        s += __shfl_xor_sync(0xffffffffu, s, 8);
        s += __shfl_xor_sync(0xffffffffu, s, 4);
        s += __shfl_xor_sync(0xffffffffu, s, 2);
        s += __shfl_xor_sync(0xffffffffu, s, 1);
        res[t] = s + bb;
    }

    if (sub == 0) {
        *(float4*)&out[e0 + hf * 4] = make_float4(res[0], res[1], res[2], res[3]);
    }
}

extern "C" void kernel_launch(void* const* d_in, const int* in_sizes, int n_in,
                              void* d_out, int out_size)
{
    const float* zsrc = (const float*)d_in[0];
    const float* zdst = (const float*)d_in[1];
    const int*   eidx = (const int*)d_in[2];
    const float* W1   = (const float*)d_in[3];
    const float* b1   = (const float*)d_in[4];
    const float* W2   = (const float*)d_in[5];
    const float* b2   = (const float*)d_in[6];
    float*       out  = (float*)d_out;

    cudaFuncSetAttribute(node_gemm_wmma, cudaFuncAttributeMaxDynamicSharedMemorySize, S_TOTAL);

    convert_w1_kernel<<<32, 256>>>(W1);

    dim3 ggrid((N_NODES + 63) / 64, 2);   // 1563 x 2
    node_gemm_wmma<<<ggrid, 256, S_TOTAL>>>(zsrc, zdst, b1);

    const int edges_per_block = (256 / 32) * 8;   // 64 edges/block
    const int eblocks = (N_EDGES + edges_per_block - 1) / edges_per_block;
    edge_kernel<<<eblocks, 256>>>(eidx, W2, b2, out);
}